// round 2
// baseline (speedup 1.0000x reference)
#include <cuda_runtime.h>

#define TPB 128
#define NS  128   // samples per block

// ---- shared memory layout (in floats) ----
#define SZ_W1T (128*68)          // W1 transposed [k=128][j=64] pad 68
#define SZ_W2T (64*36)           // W2 transposed [k=64][j=32] pad 36
#define SZ_W3T (32*4)            // W3 transposed [k=32][r=3] pad 4
#define SZ_V1T (3*36 + 4)        // V1 transposed [k=3][j=32] pad 36 (+4 align)
#define SZ_V2T (32*68)           // V2 transposed [k=32][j=64] pad 68
#define SZ_V3  (128*64)          // V3 natural [j=128][k=64]

#define OFF_W1T 0
#define OFF_W2T (OFF_W1T + SZ_W1T)
#define OFF_W3T (OFF_W2T + SZ_W2T)
#define OFF_V1T (OFF_W3T + SZ_W3T)
#define OFF_V2T (OFF_V1T + SZ_V1T)
#define OFF_V3  (OFF_V2T + SZ_V2T)
#define OFF_B1  (OFF_V3  + SZ_V3)
#define OFF_B2  (OFF_B1 + 64)
#define OFF_B3  (OFF_B2 + 32)
#define OFF_C1  (OFF_B3 + 4)
#define OFF_C2  (OFF_C1 + 32)
#define OFF_C3  (OFF_C2 + 64)
#define OFF_EW  (OFF_C3 + 128)
#define OFF_EB  (OFF_EW + 68)
#define OFF_AB  (OFF_EB + 4)          // buffer A: 128 rows x 129
#define OFF_BB  (OFF_AB + 128*129)    // buffer B: 128 rows x 129
#define SMEM_FLOATS (OFF_BB + 128*129)

__device__ __forceinline__ float sigmoidf(float v) {
    return __fdividef(1.0f, 1.0f + __expf(-v));
}

__global__ __launch_bounds__(TPB, 1)
void sindy_fused_kernel(
    const float* __restrict__ x,  const float* __restrict__ dx,
    const float* __restrict__ W1, const float* __restrict__ b1,
    const float* __restrict__ W2, const float* __restrict__ b2,
    const float* __restrict__ W3, const float* __restrict__ b3,
    const float* __restrict__ V1, const float* __restrict__ c1,
    const float* __restrict__ V2, const float* __restrict__ c2,
    const float* __restrict__ V3, const float* __restrict__ c3,
    const float* __restrict__ Ew, const float* __restrict__ Eb,
    float* __restrict__ out, int n)
{
    extern __shared__ float sm[];
    const int tid = threadIdx.x;
    const long long base = (long long)blockIdx.x * NS;

    // ---- stage weights (transposed where the hot loop wants k-major) ----
    for (int i = tid; i < 64*128; i += TPB) { int j = i >> 7, k = i & 127; sm[OFF_W1T + k*68 + j] = W1[i]; }
    for (int i = tid; i < 32*64;  i += TPB) { int j = i >> 6, k = i & 63;  sm[OFF_W2T + k*36 + j] = W2[i]; }
    for (int i = tid; i < 3*32;   i += TPB) { int j = i >> 5, k = i & 31;  sm[OFF_W3T + k*4  + j] = W3[i]; }
    for (int i = tid; i < 32*3;   i += TPB) { int j = i / 3,  k = i % 3;   sm[OFF_V1T + k*36 + j] = V1[i]; }
    for (int i = tid; i < 64*32;  i += TPB) { int j = i >> 5, k = i & 31;  sm[OFF_V2T + k*68 + j] = V2[i]; }
    for (int i = tid; i < 128*64; i += TPB) sm[OFF_V3 + i] = V3[i];
    if (tid < 64)  sm[OFF_B1 + tid] = b1[tid];
    if (tid < 32)  sm[OFF_B2 + tid] = b2[tid];
    if (tid < 3)   sm[OFF_B3 + tid] = b3[tid];
    if (tid < 32)  sm[OFF_C1 + tid] = c1[tid];
    if (tid < 64)  sm[OFF_C2 + tid] = c2[tid];
    if (tid < 128) sm[OFF_C3 + tid] = c3[tid];
    if (tid < 66)  sm[OFF_EW + tid] = Ew[tid];
    if (tid < 3)   sm[OFF_EB + tid] = Eb[tid];

    float* Abuf = sm + OFF_AB;
    float* Bbuf = sm + OFF_BB;

    long long rem = (long long)n - base;
    const int nv = (rem >= NS) ? NS : (int)rem;

    // ---- stage x, dx (coalesced float4) ----
    if (nv == NS) {
        const float4* x4  = (const float4*)(x  + base * 128);
        const float4* dx4 = (const float4*)(dx + base * 128);
        for (int i = tid; i < NS * 128 / 4; i += TPB) {
            int e = i * 4; int r = e >> 7, c = e & 127;
            float4 v = x4[i];
            float* d = &Abuf[r*129 + c];
            d[0] = v.x; d[1] = v.y; d[2] = v.z; d[3] = v.w;
            v = dx4[i];
            d = &Bbuf[r*129 + c];
            d[0] = v.x; d[1] = v.y; d[2] = v.z; d[3] = v.w;
        }
    } else {
        for (int i = tid; i < nv * 128; i += TPB) {
            int r = i >> 7, c = i & 127;
            Abuf[r*129 + c] = x[base*128 + i];
            Bbuf[r*129 + c] = dx[base*128 + i];
        }
    }
    __syncthreads();

    const size_t n3  = (size_t)n * 3;
    const size_t xbo = (size_t)n * 9;
    const size_t dxo = xbo + (size_t)n * 128;

    if (tid < nv) {
        float* Arow = Abuf + tid * 129;
        float* Brow = Bbuf + tid * 129;

        // ================= encoder layer 1: 128 -> 64 =================
        float a[64], ta[64];
        #pragma unroll
        for (int j = 0; j < 64; j++) { a[j] = sm[OFF_B1 + j]; ta[j] = 0.f; }
        for (int k = 0; k < 128; k++) {
            float xv = Arow[k], dv = Brow[k];
            const float4* w4 = (const float4*)&sm[OFF_W1T + k*68];
            #pragma unroll
            for (int j4 = 0; j4 < 16; j4++) {
                float4 w = w4[j4];
                a [j4*4+0] += w.x * xv;  ta[j4*4+0] += w.x * dv;
                a [j4*4+1] += w.y * xv;  ta[j4*4+1] += w.y * dv;
                a [j4*4+2] += w.z * xv;  ta[j4*4+2] += w.z * dv;
                a [j4*4+3] += w.w * xv;  ta[j4*4+3] += w.w * dv;
            }
        }
        #pragma unroll
        for (int j = 0; j < 64; j++) {
            float s = sigmoidf(a[j]);
            Arow[j]      = s;                       // h1
            Arow[64 + j] = s * (1.f - s) * ta[j];   // t1
        }

        // ================= encoder layer 2: 64 -> 32 =================
        float a2[32], ta2[32];
        #pragma unroll
        for (int j = 0; j < 32; j++) { a2[j] = sm[OFF_B2 + j]; ta2[j] = 0.f; }
        for (int k = 0; k < 64; k++) {
            float hv = Arow[k], tv = Arow[64 + k];
            const float4* w4 = (const float4*)&sm[OFF_W2T + k*36];
            #pragma unroll
            for (int j4 = 0; j4 < 8; j4++) {
                float4 w = w4[j4];
                a2 [j4*4+0] += w.x * hv;  ta2[j4*4+0] += w.x * tv;
                a2 [j4*4+1] += w.y * hv;  ta2[j4*4+1] += w.y * tv;
                a2 [j4*4+2] += w.z * hv;  ta2[j4*4+2] += w.z * tv;
                a2 [j4*4+3] += w.w * hv;  ta2[j4*4+3] += w.w * tv;
            }
        }
        #pragma unroll
        for (int j = 0; j < 32; j++) {
            float s = sigmoidf(a2[j]);
            Brow[j]      = s;                        // h2
            Brow[32 + j] = s * (1.f - s) * ta2[j];   // t2
        }

        // ================= encoder layer 3: 32 -> 3 (z, dz) =================
        float z0 = sm[OFF_B3+0], z1 = sm[OFF_B3+1], z2 = sm[OFF_B3+2];
        float tz0 = 0.f, tz1 = 0.f, tz2 = 0.f;
        #pragma unroll
        for (int k = 0; k < 32; k++) {
            float hv = Brow[k], tv = Brow[32 + k];
            float w0 = sm[OFF_W3T + k*4 + 0];
            float w1 = sm[OFF_W3T + k*4 + 1];
            float w2 = sm[OFF_W3T + k*4 + 2];
            z0 += w0 * hv;  tz0 += w0 * tv;
            z1 += w1 * hv;  tz1 += w1 * tv;
            z2 += w2 * hv;  tz2 += w2 * tv;
        }

        // ================= SINDy library (22 terms) + dzb =================
        float th[22];
        th[0] = 1.f; th[1] = 1.f; th[2] = 1.f;
        th[3] = z0;  th[4] = z1;  th[5] = z2;
        th[6]  = z0*z0; th[7]  = z0*z1; th[8]  = z0*z2;
        th[9]  = z1*z1; th[10] = z1*z2; th[11] = z2*z2;
        th[12] = th[6]*z0;  th[13] = th[6]*z1;  th[14] = th[6]*z2;
        th[15] = th[7]*z1;  th[16] = th[7]*z2;  th[17] = th[8]*z2;
        th[18] = th[9]*z1;  th[19] = th[9]*z2;  th[20] = th[10]*z2;
        th[21] = th[11]*z2;

        float q0 = sm[OFF_EB+0], q1 = sm[OFF_EB+1], q2 = sm[OFF_EB+2];
        #pragma unroll
        for (int k = 0; k < 22; k++) {
            q0 += sm[OFF_EW +      k] * th[k];
            q1 += sm[OFF_EW + 22 + k] * th[k];
            q2 += sm[OFF_EW + 44 + k] * th[k];
        }

        // write z, dz, dzb
        size_t sI = (size_t)(base + tid);
        out[           sI*3 + 0] = z0;  out[           sI*3 + 1] = z1;  out[           sI*3 + 2] = z2;
        out[n3       + sI*3 + 0] = tz0; out[n3       + sI*3 + 1] = tz1; out[n3       + sI*3 + 2] = tz2;
        out[2*n3     + sI*3 + 0] = q0;  out[2*n3     + sI*3 + 1] = q1;  out[2*n3     + sI*3 + 2] = q2;

        // ================= decoder layer 1: 3 -> 32 =================
        float d1[32], t1d[32];
        #pragma unroll
        for (int j = 0; j < 32; j++) { d1[j] = sm[OFF_C1 + j]; t1d[j] = 0.f; }
        #pragma unroll
        for (int k = 0; k < 3; k++) {
            float pv = (k == 0) ? z0 : ((k == 1) ? z1 : z2);
            float tv = (k == 0) ? q0 : ((k == 1) ? q1 : q2);
            const float4* w4 = (const float4*)&sm[OFF_V1T + k*36];
            #pragma unroll
            for (int j4 = 0; j4 < 8; j4++) {
                float4 w = w4[j4];
                d1 [j4*4+0] += w.x * pv;  t1d[j4*4+0] += w.x * tv;
                d1 [j4*4+1] += w.y * pv;  t1d[j4*4+1] += w.y * tv;
                d1 [j4*4+2] += w.z * pv;  t1d[j4*4+2] += w.z * tv;
                d1 [j4*4+3] += w.w * pv;  t1d[j4*4+3] += w.w * tv;
            }
        }
        #pragma unroll
        for (int j = 0; j < 32; j++) {
            float s = sigmoidf(d1[j]);
            Arow[j]      = s;                        // h1d
            Arow[32 + j] = s * (1.f - s) * t1d[j];   // t1d
        }

        // ================= decoder layer 2: 32 -> 64 =================
        float d2[64], t2d[64];
        #pragma unroll
        for (int j = 0; j < 64; j++) { d2[j] = sm[OFF_C2 + j]; t2d[j] = 0.f; }
        for (int k = 0; k < 32; k++) {
            float hv = Arow[k], tv = Arow[32 + k];
            const float4* w4 = (const float4*)&sm[OFF_V2T + k*68];
            #pragma unroll
            for (int j4 = 0; j4 < 16; j4++) {
                float4 w = w4[j4];
                d2 [j4*4+0] += w.x * hv;  t2d[j4*4+0] += w.x * tv;
                d2 [j4*4+1] += w.y * hv;  t2d[j4*4+1] += w.y * tv;
                d2 [j4*4+2] += w.z * hv;  t2d[j4*4+2] += w.z * tv;
                d2 [j4*4+3] += w.w * hv;  t2d[j4*4+3] += w.w * tv;
            }
        }
        #pragma unroll
        for (int j = 0; j < 64; j++) {
            float s = sigmoidf(d2[j]);
            d2[j]  = s;                         // h2d (keep in regs)
            t2d[j] = s * (1.f - s) * t2d[j];    // t2d (keep in regs)
        }

        // ================= decoder layer 3: 64 -> 128 (xb, dxb) =================
        for (int j = 0; j < 128; j++) {
            float acc = sm[OFF_C3 + j], tacc = 0.f;
            const float4* w4 = (const float4*)&sm[OFF_V3 + j*64];
            #pragma unroll
            for (int k4 = 0; k4 < 16; k4++) {
                float4 w = w4[k4];
                acc  += w.x * d2 [k4*4+0] + w.y * d2 [k4*4+1]
                      + w.z * d2 [k4*4+2] + w.w * d2 [k4*4+3];
                tacc += w.x * t2d[k4*4+0] + w.y * t2d[k4*4+1]
                      + w.z * t2d[k4*4+2] + w.w * t2d[k4*4+3];
            }
            Arow[j] = acc;    // xb
            Brow[j] = tacc;   // dxb
        }
    }
    __syncthreads();

    // ---- write xb, dxb coalesced ----
    if (nv == NS && (n & 3) == 0) {
        float4* ox = (float4*)(out + xbo + base * 128);
        float4* od = (float4*)(out + dxo + base * 128);
        for (int i = tid; i < NS * 128 / 4; i += TPB) {
            int e = i * 4; int r = e >> 7, c = e & 127;
            const float* ap = &Abuf[r*129 + c];
            const float* bp = &Bbuf[r*129 + c];
            float4 v; v.x = ap[0]; v.y = ap[1]; v.z = ap[2]; v.w = ap[3];
            ox[i] = v;
            v.x = bp[0]; v.y = bp[1]; v.z = bp[2]; v.w = bp[3];
            od[i] = v;
        }
    } else {
        for (int i = tid; i < nv * 128; i += TPB) {
            int r = i >> 7, c = i & 127;
            out[xbo + base*128 + i] = Abuf[r*129 + c];
            out[dxo + base*128 + i] = Bbuf[r*129 + c];
        }
    }
}

extern "C" void kernel_launch(void* const* d_in, const int* in_sizes, int n_in,
                              void* d_out, int out_size) {
    (void)n_in; (void)out_size;
    const float* x  = (const float*)d_in[0];
    const float* dx = (const float*)d_in[1];
    const float* W1 = (const float*)d_in[2];
    const float* b1 = (const float*)d_in[3];
    const float* W2 = (const float*)d_in[4];
    const float* b2 = (const float*)d_in[5];
    const float* W3 = (const float*)d_in[6];
    const float* b3 = (const float*)d_in[7];
    const float* V1 = (const float*)d_in[8];
    const float* c1 = (const float*)d_in[9];
    const float* V2 = (const float*)d_in[10];
    const float* c2 = (const float*)d_in[11];
    const float* V3 = (const float*)d_in[12];
    const float* c3 = (const float*)d_in[13];
    const float* Ew = (const float*)d_in[14];
    const float* Eb = (const float*)d_in[15];
    float* out = (float*)d_out;

    const int n = in_sizes[0] / 128;
    const size_t smem = SMEM_FLOATS * sizeof(float);
    cudaFuncSetAttribute(sindy_fused_kernel,
                         cudaFuncAttributeMaxDynamicSharedMemorySize, (int)smem);
    const int grid = (n + NS - 1) / NS;
    sindy_fused_kernel<<<grid, TPB, smem>>>(x, dx, W1, b1, W2, b2, W3, b3,
                                            V1, c1, V2, c2, V3, c3, Ew, Eb,
                                            out, n);
}